// round 5
// baseline (speedup 1.0000x reference)
#include <cuda_runtime.h>

#define NF 128
#define HID 128
#define N_NODES 10000
#define N_EDGES 640000
#define TE 64
#define KT 16
#define THREADS 256
#define INV_NORM 0.01f

__device__ __forceinline__ float silu_f(float x) {
    return x / (1.0f + __expf(-x));
}

// out region of d_out doubles as the agg accumulator ([N_NODES, HID] == [N_NODES, NF]).
__global__ void zero_out_kernel(float* __restrict__ out) {
    int i = blockIdx.x * blockDim.x + threadIdx.x;
    if (i < N_NODES * NF) out[i] = 0.0f;
}

// Edge MLP: per 64-edge tile, gather concat(h[row],h[col]) in K-panels,
// GEMM1 [64,256]x[256,128] -> SiLU -> GEMM2 [64,128]x[128,128] -> SiLU
// -> write mij, atomicAdd raw sums into agg (= out region).
__global__ __launch_bounds__(THREADS) void edge_kernel(
    const float* __restrict__ h, const int* __restrict__ ei,
    const float* __restrict__ ew1, const float* __restrict__ eb1,
    const float* __restrict__ ew2, const float* __restrict__ eb2,
    float* __restrict__ mij, float* __restrict__ agg)
{
    __shared__ float as[TE][KT];
    __shared__ float bs[KT][HID];
    __shared__ float hs[TE][HID];
    __shared__ int rs[TE];
    __shared__ int cs[TE];

    const int tid = threadIdx.x;
    const int e0 = blockIdx.x * TE;

    if (tid < TE) {
        rs[tid] = ei[e0 + tid];
        cs[tid] = ei[N_EDGES + e0 + tid];
    }
    __syncthreads();

    const int tx = tid & 15;       // 16 col-groups of 8
    const int ty = tid >> 4;       // 16 row-groups of 4
    const int r0 = ty * 4;
    const int c0 = tx * 8;

    float b1r[8], b2r[8];
#pragma unroll
    for (int j = 0; j < 8; j++) { b1r[j] = eb1[c0 + j]; b2r[j] = eb2[c0 + j]; }

    float acc[4][8];
#pragma unroll
    for (int i = 0; i < 4; i++)
#pragma unroll
        for (int j = 0; j < 8; j++) acc[i][j] = 0.0f;

    // ---- GEMM1: K = 2*NF = 256 ----
    for (int k0 = 0; k0 < 2 * NF; k0 += KT) {
        __syncthreads();
        // gather A panel: 64 edges x 16 k  (one float4 per thread)
        {
            int e  = tid >> 2;
            int kq = (tid & 3) * 4;
            int node = (k0 < NF) ? rs[e] : cs[e];
            const float4 v = *(const float4*)(h + node * NF + (k0 & (NF - 1)) + kq);
            *(float4*)&as[e][kq] = v;
        }
        // load B panel: 16 x 128 (two float4 per thread)
        {
#pragma unroll
            for (int j = 0; j < 2; j++) {
                int lin = tid + j * THREADS;     // float4 index over 16*32
                int k = lin >> 5, c4 = (lin & 31) * 4;
                *(float4*)&bs[k][c4] = *(const float4*)(ew1 + (k0 + k) * HID + c4);
            }
        }
        __syncthreads();
#pragma unroll
        for (int k = 0; k < KT; k++) {
            float a0 = as[r0 + 0][k];
            float a1 = as[r0 + 1][k];
            float a2 = as[r0 + 2][k];
            float a3 = as[r0 + 3][k];
            float4 b0 = *(float4*)&bs[k][c0];
            float4 b1 = *(float4*)&bs[k][c0 + 4];
            float bb[8] = {b0.x, b0.y, b0.z, b0.w, b1.x, b1.y, b1.z, b1.w};
#pragma unroll
            for (int j = 0; j < 8; j++) {
                acc[0][j] = fmaf(a0, bb[j], acc[0][j]);
                acc[1][j] = fmaf(a1, bb[j], acc[1][j]);
                acc[2][j] = fmaf(a2, bb[j], acc[2][j]);
                acc[3][j] = fmaf(a3, bb[j], acc[3][j]);
            }
        }
    }

    // epilogue 1: bias + SiLU -> hs
#pragma unroll
    for (int i = 0; i < 4; i++) {
#pragma unroll
        for (int j = 0; j < 8; j++) {
            hs[r0 + i][c0 + j] = silu_f(acc[i][j] + b1r[j]);
            acc[i][j] = 0.0f;
        }
    }

    // ---- GEMM2: K = HID = 128 ----
    for (int k0 = 0; k0 < HID; k0 += KT) {
        __syncthreads();
        {
#pragma unroll
            for (int j = 0; j < 2; j++) {
                int lin = tid + j * THREADS;
                int k = lin >> 5, c4 = (lin & 31) * 4;
                *(float4*)&bs[k][c4] = *(const float4*)(ew2 + (k0 + k) * HID + c4);
            }
        }
        __syncthreads();
#pragma unroll
        for (int k = 0; k < KT; k++) {
            float a0 = hs[r0 + 0][k0 + k];
            float a1 = hs[r0 + 1][k0 + k];
            float a2 = hs[r0 + 2][k0 + k];
            float a3 = hs[r0 + 3][k0 + k];
            float4 b0 = *(float4*)&bs[k][c0];
            float4 b1 = *(float4*)&bs[k][c0 + 4];
            float bb[8] = {b0.x, b0.y, b0.z, b0.w, b1.x, b1.y, b1.z, b1.w};
#pragma unroll
            for (int j = 0; j < 8; j++) {
                acc[0][j] = fmaf(a0, bb[j], acc[0][j]);
                acc[1][j] = fmaf(a1, bb[j], acc[1][j]);
                acc[2][j] = fmaf(a2, bb[j], acc[2][j]);
                acc[3][j] = fmaf(a3, bb[j], acc[3][j]);
            }
        }
    }

    // epilogue 2: bias + SiLU -> mij store + scatter atomicAdd into agg
#pragma unroll
    for (int i = 0; i < 4; i++) {
        int r = r0 + i;
        int e = e0 + r;
        int node = rs[r];
#pragma unroll
        for (int jj = 0; jj < 8; jj += 4) {
            float4 v;
            v.x = silu_f(acc[i][jj + 0] + b2r[jj + 0]);
            v.y = silu_f(acc[i][jj + 1] + b2r[jj + 1]);
            v.z = silu_f(acc[i][jj + 2] + b2r[jj + 2]);
            v.w = silu_f(acc[i][jj + 3] + b2r[jj + 3]);
            *(float4*)(mij + (size_t)e * HID + c0 + jj) = v;
            float* ap = agg + (size_t)node * HID + c0 + jj;
            atomicAdd(ap + 0, v.x);
            atomicAdd(ap + 1, v.y);
            atomicAdd(ap + 2, v.z);
            atomicAdd(ap + 3, v.w);
        }
    }
}

// Node MLP: a = concat(h, agg/NORM); out = h + silu(a@nw1+nb1)@nw2 + nb2
// agg is read from `out` (raw sums), final result overwrites `out` in place.
// Each block reads only its own 64 rows before writing them — no cross-block hazard.
__global__ __launch_bounds__(THREADS) void node_kernel(
    const float* __restrict__ h,
    const float* __restrict__ nw1, const float* __restrict__ nb1,
    const float* __restrict__ nw2, const float* __restrict__ nb2,
    float* __restrict__ out)
{
    __shared__ float as[TE][KT];
    __shared__ float bs[KT][HID];
    __shared__ float hs[TE][HID];

    const int tid = threadIdx.x;
    const int v0 = blockIdx.x * TE;

    const int tx = tid & 15;
    const int ty = tid >> 4;
    const int r0 = ty * 4;
    const int c0 = tx * 8;

    float b1r[8], b2r[8];
#pragma unroll
    for (int j = 0; j < 8; j++) { b1r[j] = nb1[c0 + j]; b2r[j] = nb2[c0 + j]; }

    float acc[4][8];
#pragma unroll
    for (int i = 0; i < 4; i++)
#pragma unroll
        for (int j = 0; j < 8; j++) acc[i][j] = 0.0f;

    // ---- GEMM1: K = NF + HID = 256 ----
    for (int k0 = 0; k0 < NF + HID; k0 += KT) {
        __syncthreads();
        {
            int e  = tid >> 2;
            int kq = (tid & 3) * 4;
            int node = v0 + e;
            if (node >= N_NODES) node = N_NODES - 1;   // clamp loads; stores guarded
            float4 v;
            if (k0 < NF) {
                v = *(const float4*)(h + node * NF + k0 + kq);
            } else {
                v = *(const float4*)(out + (size_t)node * HID + (k0 - NF) + kq);
                v.x *= INV_NORM; v.y *= INV_NORM; v.z *= INV_NORM; v.w *= INV_NORM;
            }
            *(float4*)&as[e][kq] = v;
        }
        {
#pragma unroll
            for (int j = 0; j < 2; j++) {
                int lin = tid + j * THREADS;
                int k = lin >> 5, c4 = (lin & 31) * 4;
                *(float4*)&bs[k][c4] = *(const float4*)(nw1 + (k0 + k) * HID + c4);
            }
        }
        __syncthreads();
#pragma unroll
        for (int k = 0; k < KT; k++) {
            float a0 = as[r0 + 0][k];
            float a1 = as[r0 + 1][k];
            float a2 = as[r0 + 2][k];
            float a3 = as[r0 + 3][k];
            float4 b0 = *(float4*)&bs[k][c0];
            float4 b1 = *(float4*)&bs[k][c0 + 4];
            float bb[8] = {b0.x, b0.y, b0.z, b0.w, b1.x, b1.y, b1.z, b1.w};
#pragma unroll
            for (int j = 0; j < 8; j++) {
                acc[0][j] = fmaf(a0, bb[j], acc[0][j]);
                acc[1][j] = fmaf(a1, bb[j], acc[1][j]);
                acc[2][j] = fmaf(a2, bb[j], acc[2][j]);
                acc[3][j] = fmaf(a3, bb[j], acc[3][j]);
            }
        }
    }

    // epilogue 1: bias + SiLU -> hs
#pragma unroll
    for (int i = 0; i < 4; i++) {
#pragma unroll
        for (int j = 0; j < 8; j++) {
            hs[r0 + i][c0 + j] = silu_f(acc[i][j] + b1r[j]);
            acc[i][j] = 0.0f;
        }
    }

    // all reads of the agg region for this block's rows complete before overwrite
    __syncthreads();

    // ---- GEMM2: K = HID = 128 (no SiLU, residual + nb2) ----
    for (int k0 = 0; k0 < HID; k0 += KT) {
        __syncthreads();
        {
#pragma unroll
            for (int j = 0; j < 2; j++) {
                int lin = tid + j * THREADS;
                int k = lin >> 5, c4 = (lin & 31) * 4;
                *(float4*)&bs[k][c4] = *(const float4*)(nw2 + (k0 + k) * HID + c4);
            }
        }
        __syncthreads();
#pragma unroll
        for (int k = 0; k < KT; k++) {
            float a0 = hs[r0 + 0][k0 + k];
            float a1 = hs[r0 + 1][k0 + k];
            float a2 = hs[r0 + 2][k0 + k];
            float a3 = hs[r0 + 3][k0 + k];
            float4 b0 = *(float4*)&bs[k][c0];
            float4 b1 = *(float4*)&bs[k][c0 + 4];
            float bb[8] = {b0.x, b0.y, b0.z, b0.w, b1.x, b1.y, b1.z, b1.w};
#pragma unroll
            for (int j = 0; j < 8; j++) {
                acc[0][j] = fmaf(a0, bb[j], acc[0][j]);
                acc[1][j] = fmaf(a1, bb[j], acc[1][j]);
                acc[2][j] = fmaf(a2, bb[j], acc[2][j]);
                acc[3][j] = fmaf(a3, bb[j], acc[3][j]);
            }
        }
    }

#pragma unroll
    for (int i = 0; i < 4; i++) {
        int node = v0 + r0 + i;
        if (node < N_NODES) {
#pragma unroll
            for (int jj = 0; jj < 8; jj += 4) {
                int c = c0 + jj;
                const float4 hv = *(const float4*)(h + node * NF + c);
                float4 v;
                v.x = hv.x + acc[i][jj + 0] + b2r[jj + 0];
                v.y = hv.y + acc[i][jj + 1] + b2r[jj + 1];
                v.z = hv.z + acc[i][jj + 2] + b2r[jj + 2];
                v.w = hv.w + acc[i][jj + 3] + b2r[jj + 3];
                *(float4*)(out + (size_t)node * NF + c) = v;
            }
        }
    }
}

extern "C" void kernel_launch(void* const* d_in, const int* in_sizes, int n_in,
                              void* d_out, int out_size) {
    const float* h   = (const float*)d_in[0];
    const int*   ei  = (const int*)d_in[1];     // int32 [2, N_EDGES] per harness dtype rules
    const float* ew1 = (const float*)d_in[2];
    const float* eb1 = (const float*)d_in[3];
    const float* ew2 = (const float*)d_in[4];
    const float* eb2 = (const float*)d_in[5];
    const float* nw1 = (const float*)d_in[6];
    const float* nb1 = (const float*)d_in[7];
    const float* nw2 = (const float*)d_in[8];
    const float* nb2 = (const float*)d_in[9];

    float* out = (float*)d_out;                      // [N_NODES, NF] (also agg scratch)
    float* mij = out + (size_t)N_NODES * NF;         // [N_EDGES, HID]

    zero_out_kernel<<<(N_NODES * NF + 255) / 256, 256>>>(out);
    edge_kernel<<<N_EDGES / TE, THREADS>>>(h, ei, ew1, eb1, ew2, eb2, mij, out);
    node_kernel<<<(N_NODES + TE - 1) / TE, THREADS>>>(h, nw1, nb1, nw2, nb2, out);
}

// round 8
// speedup vs baseline: 1.5467x; 1.5467x over previous
#include <cuda_runtime.h>

#define NF 128
#define HID 128
#define N_NODES 10000
#define N_EDGES 640000
#define THREADS 256
#define INV_NORM 0.01f

// ---- SMEM layout (float offsets) ----
#define AS_STRIDE 36    // 32 k + 4 pad; 144B rows (16B-aligned), stride%32==4 -> conflict-free frags
#define BS_STRIDE 136   // 128 n + 8 pad; stride%32==8 -> conflict-free frags
#define AS_OFF 0                          // 128*36   (also P chunk 0 / stage 0)
#define BS_OFF (128 * AS_STRIDE)          // 32*136
#define P1_OFF (BS_OFF + 32 * BS_STRIDE)
#define P2_OFF (P1_OFF + 128 * AS_STRIDE)
#define P3_OFF (P2_OFF + 128 * AS_STRIDE)
#define RS_OFF (P3_OFF + 128 * AS_STRIDE)
#define CS_OFF (RS_OFF + 128)
#define SMEM_FLOATS (CS_OFF + 128)
#define SMEM_BYTES (SMEM_FLOATS * 4)      // ~92KB

__device__ __forceinline__ float silu_f(float x) { return x / (1.0f + __expf(-x)); }

__device__ __forceinline__ unsigned tf32_of(float f) {
    unsigned r;
    asm("cvt.rna.tf32.f32 %0, %1;" : "=r"(r) : "f"(f));
    return r;
}

// D(16x8) += A(16x8) * B(8x8), tf32 inputs as raw b32
__device__ __forceinline__ void mma8(float* c, const unsigned* a, const unsigned* b) {
    asm volatile(
        "mma.sync.aligned.m16n8k8.row.col.f32.tf32.tf32.f32 "
        "{%0,%1,%2,%3}, {%4,%5,%6,%7}, {%8,%9}, {%0,%1,%2,%3};"
        : "+f"(c[0]), "+f"(c[1]), "+f"(c[2]), "+f"(c[3])
        : "r"(a[0]), "r"(a[1]), "r"(a[2]), "r"(a[3]), "r"(b[0]), "r"(b[1]));
}

__global__ void zero_out_kernel(float* __restrict__ out) {
    int i = blockIdx.x * blockDim.x + threadIdx.x;
    if (i < N_NODES * NF) out[i] = 0.0f;
}

// Edge MLP via mma.sync tf32. 128 edges/CTA, 8 warps = 2(m) x 4(n).
__global__ __launch_bounds__(THREADS, 1) void edge_kernel_mma(
    const float* __restrict__ h, const int* __restrict__ ei,
    const float* __restrict__ ew1, const float* __restrict__ eb1,
    const float* __restrict__ ew2, const float* __restrict__ eb2,
    float* __restrict__ mij, float* __restrict__ agg)
{
    extern __shared__ float sm[];
    int* rs = (int*)(sm + RS_OFF);
    int* cs = (int*)(sm + CS_OFF);

    const int tid = threadIdx.x;
    const int wid = tid >> 5, lane = tid & 31;
    const int g = lane >> 2, t = lane & 3;       // quad group / thread-in-group
    const int mg = wid & 1, ng = wid >> 1;       // warp tile coords
    const int e0 = blockIdx.x * 128;

    if (tid < 128) {
        rs[tid] = ei[e0 + tid];
        cs[tid] = ei[N_EDGES + e0 + tid];
    }
    __syncthreads();

    // loader mappings
    const int lr = tid >> 1, lkh = (tid & 1) * 16;   // A gather: row, k-half
    const int lbk = tid >> 3, lbn = (tid & 7) * 16;  // B: k row, n base

    float4 aF[4], bF[4];
    {   // prefetch chunk 0
        const float* hp = h + (size_t)rs[lr] * NF + lkh;
        aF[0] = *(const float4*)(hp);      aF[1] = *(const float4*)(hp + 4);
        aF[2] = *(const float4*)(hp + 8);  aF[3] = *(const float4*)(hp + 12);
        const float* wp = ew1 + (size_t)lbk * HID + lbn;
        bF[0] = *(const float4*)(wp);      bF[1] = *(const float4*)(wp + 4);
        bF[2] = *(const float4*)(wp + 8);  bF[3] = *(const float4*)(wp + 12);
    }

    float acc[4][4][4];
#pragma unroll
    for (int mt = 0; mt < 4; mt++)
#pragma unroll
        for (int nt = 0; nt < 4; nt++)
#pragma unroll
            for (int j = 0; j < 4; j++) acc[mt][nt][j] = 0.0f;

    float* const pch0 = sm + AS_OFF;
    float* const pch1 = sm + P1_OFF;
    float* const pch2 = sm + P2_OFF;
    float* const pch3 = sm + P3_OFF;

    // ================= GEMM1: K = 256, 8 chunks of 32 =================
#pragma unroll 1
    for (int kc = 0; kc < 8; kc++) {
        // STS A (tf32) + B (tf32)
#pragma unroll
        for (int q = 0; q < 4; q++) {
            uint4 v;
            v.x = tf32_of(aF[q].x); v.y = tf32_of(aF[q].y);
            v.z = tf32_of(aF[q].z); v.w = tf32_of(aF[q].w);
            *(uint4*)(sm + AS_OFF + lr * AS_STRIDE + lkh + 4 * q) = v;
        }
#pragma unroll
        for (int q = 0; q < 4; q++) {
            uint4 v;
            v.x = tf32_of(bF[q].x); v.y = tf32_of(bF[q].y);
            v.z = tf32_of(bF[q].z); v.w = tf32_of(bF[q].w);
            *(uint4*)(sm + BS_OFF + lbk * BS_STRIDE + lbn + 4 * q) = v;
        }
        __syncthreads();
        if (kc < 7) {   // prefetch next chunk
            int kn = kc + 1;
            int node = (kn < 4) ? rs[lr] : cs[lr];
            const float* hp = h + (size_t)node * NF + (kn & 3) * 32 + lkh;
            aF[0] = *(const float4*)(hp);      aF[1] = *(const float4*)(hp + 4);
            aF[2] = *(const float4*)(hp + 8);  aF[3] = *(const float4*)(hp + 12);
            const float* wp = ew1 + (size_t)(kn * 32 + lbk) * HID + lbn;
            bF[0] = *(const float4*)(wp);      bF[1] = *(const float4*)(wp + 4);
            bF[2] = *(const float4*)(wp + 8);  bF[3] = *(const float4*)(wp + 12);
        } else {        // prefetch GEMM2 B chunk 0
            const float* wp = ew2 + (size_t)lbk * HID + lbn;
            bF[0] = *(const float4*)(wp);      bF[1] = *(const float4*)(wp + 4);
            bF[2] = *(const float4*)(wp + 8);  bF[3] = *(const float4*)(wp + 12);
        }
        // mma phase: 4 ksteps x (4mt x 4nt)
#pragma unroll
        for (int ks = 0; ks < 4; ks++) {
            unsigned a[4][4], b[4][2];
            const float* arow = sm + AS_OFF + (mg * 64 + g) * AS_STRIDE + ks * 8 + t;
#pragma unroll
            for (int mt = 0; mt < 4; mt++) {
                const float* ap = arow + mt * 16 * AS_STRIDE;
                a[mt][0] = __float_as_uint(ap[0]);
                a[mt][1] = __float_as_uint(ap[8 * AS_STRIDE]);
                a[mt][2] = __float_as_uint(ap[4]);
                a[mt][3] = __float_as_uint(ap[8 * AS_STRIDE + 4]);
            }
            const float* bp = sm + BS_OFF + (ks * 8 + t) * BS_STRIDE + ng * 32 + g;
#pragma unroll
            for (int nt = 0; nt < 4; nt++) {
                b[nt][0] = __float_as_uint(bp[nt * 8]);
                b[nt][1] = __float_as_uint(bp[4 * BS_STRIDE + nt * 8]);
            }
#pragma unroll
            for (int mt = 0; mt < 4; mt++)
#pragma unroll
                for (int nt = 0; nt < 4; nt++)
                    mma8(acc[mt][nt], a[mt], b[nt]);
        }
        __syncthreads();
    }

    // ===== epilogue1: bias + SiLU -> P chunks (tf32, fragment-friendly layout) =====
    {
        float* pc = (ng == 0) ? pch0 : (ng == 1) ? pch1 : (ng == 2) ? pch2 : pch3;
#pragma unroll
        for (int mt = 0; mt < 4; mt++) {
#pragma unroll
            for (int nt = 0; nt < 4; nt++) {
                int colb = ng * 32 + nt * 8 + 2 * t;
                float bz0 = __ldg(eb1 + colb), bz1 = __ldg(eb1 + colb + 1);
                int r0 = mg * 64 + mt * 16 + g;
                uint2 v0, v1;
                v0.x = tf32_of(silu_f(acc[mt][nt][0] + bz0));
                v0.y = tf32_of(silu_f(acc[mt][nt][1] + bz1));
                v1.x = tf32_of(silu_f(acc[mt][nt][2] + bz0));
                v1.y = tf32_of(silu_f(acc[mt][nt][3] + bz1));
                *(uint2*)(pc + r0 * AS_STRIDE + nt * 8 + 2 * t) = v0;
                *(uint2*)(pc + (r0 + 8) * AS_STRIDE + nt * 8 + 2 * t) = v1;
                acc[mt][nt][0] = 0.0f; acc[mt][nt][1] = 0.0f;
                acc[mt][nt][2] = 0.0f; acc[mt][nt][3] = 0.0f;
            }
        }
    }
    __syncthreads();

    // ================= GEMM2: K = 128, 4 chunks; A = P (SMEM) =================
#pragma unroll 1
    for (int c = 0; c < 4; c++) {
#pragma unroll
        for (int q = 0; q < 4; q++) {
            uint4 v;
            v.x = tf32_of(bF[q].x); v.y = tf32_of(bF[q].y);
            v.z = tf32_of(bF[q].z); v.w = tf32_of(bF[q].w);
            *(uint4*)(sm + BS_OFF + lbk * BS_STRIDE + lbn + 4 * q) = v;
        }
        __syncthreads();
        if (c < 3) {
            const float* wp = ew2 + (size_t)((c + 1) * 32 + lbk) * HID + lbn;
            bF[0] = *(const float4*)(wp);      bF[1] = *(const float4*)(wp + 4);
            bF[2] = *(const float4*)(wp + 8);  bF[3] = *(const float4*)(wp + 12);
        }
        const float* pc = (c == 0) ? pch0 : (c == 1) ? pch1 : (c == 2) ? pch2 : pch3;
#pragma unroll
        for (int ks = 0; ks < 4; ks++) {
            unsigned a[4][4], b[4][2];
            const float* arow = pc + (mg * 64 + g) * AS_STRIDE + ks * 8 + t;
#pragma unroll
            for (int mt = 0; mt < 4; mt++) {
                const float* ap = arow + mt * 16 * AS_STRIDE;
                a[mt][0] = __float_as_uint(ap[0]);
                a[mt][1] = __float_as_uint(ap[8 * AS_STRIDE]);
                a[mt][2] = __float_as_uint(ap[4]);
                a[mt][3] = __float_as_uint(ap[8 * AS_STRIDE + 4]);
            }
            const float* bp = sm + BS_OFF + (ks * 8 + t) * BS_STRIDE + ng * 32 + g;
#pragma unroll
            for (int nt = 0; nt < 4; nt++) {
                b[nt][0] = __float_as_uint(bp[nt * 8]);
                b[nt][1] = __float_as_uint(bp[4 * BS_STRIDE + nt * 8]);
            }
#pragma unroll
            for (int mt = 0; mt < 4; mt++)
#pragma unroll
                for (int nt = 0; nt < 4; nt++)
                    mma8(acc[mt][nt], a[mt], b[nt]);
        }
        __syncthreads();
    }

    // ===== epilogue2: bias + SiLU -> stage (fp32) -> coalesced mij + atomics =====
#pragma unroll 1
    for (int c = 0; c < 4; c++) {
        float* pc = (c == 0) ? pch0 : (c == 1) ? pch1 : (c == 2) ? pch2 : pch3;
        if (ng == c) {
#pragma unroll
            for (int mt = 0; mt < 4; mt++) {
#pragma unroll
                for (int nt = 0; nt < 4; nt++) {
                    int colb = ng * 32 + nt * 8 + 2 * t;
                    float bz0 = __ldg(eb2 + colb), bz1 = __ldg(eb2 + colb + 1);
                    int r0 = mg * 64 + mt * 16 + g;
                    float2 v0, v1;
                    v0.x = silu_f(acc[mt][nt][0] + bz0);
                    v0.y = silu_f(acc[mt][nt][1] + bz1);
                    v1.x = silu_f(acc[mt][nt][2] + bz0);
                    v1.y = silu_f(acc[mt][nt][3] + bz1);
                    *(float2*)(pc + r0 * AS_STRIDE + nt * 8 + 2 * t) = v0;
                    *(float2*)(pc + (r0 + 8) * AS_STRIDE + nt * 8 + 2 * t) = v1;
                }
            }
        }
        __syncthreads();
        // cooperative: warp w handles rows w*16..w*16+15; lane = column
#pragma unroll 1
        for (int i = 0; i < 16; i++) {
            int r = wid * 16 + i;
            float v = pc[r * AS_STRIDE + lane];
            mij[(size_t)(e0 + r) * HID + c * 32 + lane] = v;
            atomicAdd(agg + (size_t)rs[r] * HID + c * 32 + lane, v);
        }
        __syncthreads();
    }
}

// Node MLP (fp32 FFMA, small): a = concat(h, agg/NORM); out = h + silu(a@nw1+nb1)@nw2 + nb2
#define TE 64
#define KT 16
__global__ __launch_bounds__(THREADS) void node_kernel(
    const float* __restrict__ h,
    const float* __restrict__ nw1, const float* __restrict__ nb1,
    const float* __restrict__ nw2, const float* __restrict__ nb2,
    float* __restrict__ out)
{
    __shared__ float as[TE][KT];
    __shared__ float bs[KT][HID];
    __shared__ float hs[TE][HID];

    const int tid = threadIdx.x;
    const int v0 = blockIdx.x * TE;
    const int tx = tid & 15;
    const int ty = tid >> 4;
    const int r0 = ty * 4;
    const int c0 = tx * 8;

    float b1r[8], b2r[8];
#pragma unroll
    for (int j = 0; j < 8; j++) { b1r[j] = nb1[c0 + j]; b2r[j] = nb2[c0 + j]; }

    float acc[4][8];
#pragma unroll
    for (int i = 0; i < 4; i++)
#pragma unroll
        for (int j = 0; j < 8; j++) acc[i][j] = 0.0f;

    for (int k0 = 0; k0 < NF + HID; k0 += KT) {
        __syncthreads();
        {
            int e = tid >> 2;
            int kq = (tid & 3) * 4;
            int node = v0 + e;
            if (node >= N_NODES) node = N_NODES - 1;
            float4 v;
            if (k0 < NF) {
                v = *(const float4*)(h + node * NF + k0 + kq);
            } else {
                v = *(const float4*)(out + (size_t)node * HID + (k0 - NF) + kq);
                v.x *= INV_NORM; v.y *= INV_NORM; v.z *= INV_NORM; v.w *= INV_NORM;
            }
            *(float4*)&as[e][kq] = v;
        }
#pragma unroll
        for (int j = 0; j < 2; j++) {
            int lin = tid + j * THREADS;
            int k = lin >> 5, c4 = (lin & 31) * 4;
            *(float4*)&bs[k][c4] = *(const float4*)(nw1 + (k0 + k) * HID + c4);
        }
        __syncthreads();
#pragma unroll
        for (int k = 0; k < KT; k++) {
            float a0 = as[r0 + 0][k], a1 = as[r0 + 1][k];
            float a2 = as[r0 + 2][k], a3 = as[r0 + 3][k];
            float4 b0 = *(float4*)&bs[k][c0];
            float4 b1 = *(float4*)&bs[k][c0 + 4];
            float bb[8] = {b0.x, b0.y, b0.z, b0.w, b1.x, b1.y, b1.z, b1.w};
#pragma unroll
            for (int j = 0; j < 8; j++) {
                acc[0][j] = fmaf(a0, bb[j], acc[0][j]);
                acc[1][j] = fmaf(a1, bb[j], acc[1][j]);
                acc[2][j] = fmaf(a2, bb[j], acc[2][j]);
                acc[3][j] = fmaf(a3, bb[j], acc[3][j]);
            }
        }
    }

#pragma unroll
    for (int i = 0; i < 4; i++)
#pragma unroll
        for (int j = 0; j < 8; j++) {
            hs[r0 + i][c0 + j] = silu_f(acc[i][j] + b1r[j]);
            acc[i][j] = 0.0f;
        }
    __syncthreads();

    for (int k0 = 0; k0 < HID; k0 += KT) {
        __syncthreads();
#pragma unroll
        for (int j = 0; j < 2; j++) {
            int lin = tid + j * THREADS;
            int k = lin >> 5, c4 = (lin & 31) * 4;
            *(float4*)&bs[k][c4] = *(const float4*)(nw2 + (k0 + k) * HID + c4);
        }
        __syncthreads();
#pragma unroll
        for (int k = 0; k < KT; k++) {
            float a0 = hs[r0 + 0][k0 + k], a1 = hs[r0 + 1][k0 + k];
            float a2 = hs[r0 + 2][k0 + k], a3 = hs[r0 + 3][k0 + k];
            float4 b0 = *(float4*)&bs[k][c0];
            float4 b1 = *(float4*)&bs[k][c0 + 4];
            float bb[8] = {b0.x, b0.y, b0.z, b0.w, b1.x, b1.y, b1.z, b1.w};
#pragma unroll
            for (int j = 0; j < 8; j++) {
                acc[0][j] = fmaf(a0, bb[j], acc[0][j]);
                acc[1][j] = fmaf(a1, bb[j], acc[1][j]);
                acc[2][j] = fmaf(a2, bb[j], acc[2][j]);
                acc[3][j] = fmaf(a3, bb[j], acc[3][j]);
            }
        }
    }

#pragma unroll
    for (int i = 0; i < 4; i++) {
        int node = v0 + r0 + i;
        if (node < N_NODES) {
#pragma unroll
            for (int jj = 0; jj < 8; jj += 4) {
                int c = c0 + jj;
                const float4 hv = *(const float4*)(h + node * NF + c);
                float4 v;
                v.x = hv.x + acc[i][jj + 0] + b2r[jj + 0];
                v.y = hv.y + acc[i][jj + 1] + b2r[jj + 1];
                v.z = hv.z + acc[i][jj + 2] + b2r[jj + 2];
                v.w = hv.w + acc[i][jj + 3] + b2r[jj + 3];
                *(float4*)(out + (size_t)node * NF + c) = v;
            }
        }
    }
}

extern "C" void kernel_launch(void* const* d_in, const int* in_sizes, int n_in,
                              void* d_out, int out_size) {
    const float* h   = (const float*)d_in[0];
    const int*   ei  = (const int*)d_in[1];     // int32 [2, N_EDGES]
    const float* ew1 = (const float*)d_in[2];
    const float* eb1 = (const float*)d_in[3];
    const float* ew2 = (const float*)d_in[4];
    const float* eb2 = (const float*)d_in[5];
    const float* nw1 = (const float*)d_in[6];
    const float* nb1 = (const float*)d_in[7];
    const float* nw2 = (const float*)d_in[8];
    const float* nb2 = (const float*)d_in[9];

    float* out = (float*)d_out;                  // [N_NODES, NF] (also agg scratch)
    float* mij = out + (size_t)N_NODES * NF;     // [N_EDGES, HID]

    cudaFuncSetAttribute(edge_kernel_mma, cudaFuncAttributeMaxDynamicSharedMemorySize,
                         SMEM_BYTES);

    zero_out_kernel<<<(N_NODES * NF + 255) / 256, 256>>>(out);
    edge_kernel_mma<<<N_EDGES / 128, THREADS, SMEM_BYTES>>>(h, ei, ew1, eb1, ew2, eb2,
                                                            mij, out);
    node_kernel<<<(N_NODES + TE - 1) / TE, THREADS>>>(h, nw1, nb1, nw2, nb2, out);
}

// round 14
// speedup vs baseline: 1.7208x; 1.1126x over previous
#include <cuda_runtime.h>

#define NF 128
#define HID 128
#define N_NODES 10000
#define N_EDGES 640000
#define THREADS 256
#define INV_NORM 0.01f

// ---- SMEM layout (float offsets) ----
#define AS_STRIDE 36       // 32 k + 4 pad; %32==4 -> conflict-free A frags
#define BS_STRIDE 136      // 128 n + 8 pad; %32==8 -> conflict-free B frags
#define STAGE_A_FLOATS (128 * AS_STRIDE)                 // 4608
#define STAGE_FLOATS   (STAGE_A_FLOATS + 32 * BS_STRIDE) // 8960 (A + B)
#define NSTAGE 4
#define P_OFF  (NSTAGE * STAGE_FLOATS)                   // 35840
#define PCH_FLOATS (128 * AS_STRIDE)                     // 4608 per P chunk
#define RS_OFF (P_OFF + 4 * PCH_FLOATS)                  // 54272
#define CS_OFF (RS_OFF + 128)
#define SMEM_FLOATS (CS_OFF + 128)                       // 54528
#define SMEM_BYTES (SMEM_FLOATS * 4)                     // 218112 B

// tf32 scratch (pre-converted once per launch)
__device__ unsigned g_h_t[N_NODES * NF];
__device__ unsigned g_w1_t[2 * NF * HID];
__device__ unsigned g_w2_t[HID * HID];

__device__ __forceinline__ float silu_f(float x) { return x / (1.0f + __expf(-x)); }

__device__ __forceinline__ unsigned tf32_of(float f) {
    unsigned r;
    asm("cvt.rna.tf32.f32 %0, %1;" : "=r"(r) : "f"(f));
    return r;
}

__device__ __forceinline__ unsigned smem_u32(const void* p) {
    unsigned a;
    asm("{ .reg .u64 t; cvta.to.shared.u64 t, %1; cvt.u32.u64 %0, t; }" : "=r"(a) : "l"(p));
    return a;
}

__device__ __forceinline__ void cpa16(unsigned dst, const void* src) {
    asm volatile("cp.async.ca.shared.global [%0], [%1], 16;" :: "r"(dst), "l"(src));
}
#define CP_COMMIT() asm volatile("cp.async.commit_group;" ::: "memory")
#define CP_WAIT2()  asm volatile("cp.async.wait_group 2;" ::: "memory")

// D(16x8) += A(16x8) * B(8x8), tf32 inputs as raw b32
__device__ __forceinline__ void mma8(float* c, const unsigned* a, const unsigned* b) {
    asm volatile(
        "mma.sync.aligned.m16n8k8.row.col.f32.tf32.tf32.f32 "
        "{%0,%1,%2,%3}, {%4,%5,%6,%7}, {%8,%9}, {%0,%1,%2,%3};"
        : "+f"(c[0]), "+f"(c[1]), "+f"(c[2]), "+f"(c[3])
        : "r"(a[0]), "r"(a[1]), "r"(a[2]), "r"(a[3]), "r"(b[0]), "r"(b[1]));
}

// Fused prep: convert h/ew1/ew2 to tf32 scratch + zero agg (= out region).
__global__ void prep_kernel(const float* __restrict__ h,
                            const float* __restrict__ ew1,
                            const float* __restrict__ ew2,
                            float* __restrict__ out) {
    int i = blockIdx.x * blockDim.x + threadIdx.x;
    if (i < N_NODES * NF) {
        g_h_t[i] = tf32_of(h[i]);
        out[i] = 0.0f;
    }
    if (i < 2 * NF * HID) g_w1_t[i] = tf32_of(ew1[i]);
    if (i < HID * HID)    g_w2_t[i] = tf32_of(ew2[i]);
}

// Edge MLP via mma.sync tf32 + cp.async 4-stage pipeline. 128 edges/CTA, 8 warps = 2(m) x 4(n).
__global__ __launch_bounds__(THREADS, 1) void edge_kernel_mma(
    const int* __restrict__ ei,
    const float* __restrict__ eb1, const float* __restrict__ eb2,
    float* __restrict__ mij, float* __restrict__ agg)
{
    extern __shared__ float sm[];
    int* rs = (int*)(sm + RS_OFF);
    int* cs = (int*)(sm + CS_OFF);
    const unsigned sbase = smem_u32(sm);

    const int tid = threadIdx.x;
    const int wid = tid >> 5, lane = tid & 31;
    const int g = lane >> 2, t = lane & 3;
    const int mg = wid & 1, ng = wid >> 1;
    const int e0 = blockIdx.x * 128;

    if (tid < 128) {
        rs[tid] = ei[e0 + tid];
        cs[tid] = ei[N_EDGES + e0 + tid];
    }
    __syncthreads();

    // loader mappings
    const int lr = tid >> 1, lkh = (tid & 1) * 16;   // A: row, 16-float half
    const int lbk = tid >> 3, lbn = (tid & 7) * 16;  // B: k row, n base

    // issue cp.async for logical chunk kc (0..7: A+B GEMM1; 8..11: B GEMM2; >=12: empty)
    auto issue_chunk = [&](int kc) {
        if (kc < 12) {
            unsigned sA = sbase + (kc & 3) * (STAGE_FLOATS * 4);
            unsigned sB = sA + STAGE_A_FLOATS * 4;
            if (kc < 8) {
                int node = (kc < 4) ? rs[lr] : cs[lr];
                const unsigned* hp = g_h_t + (size_t)node * NF + (kc & 3) * 32 + lkh;
                unsigned dA = sA + (lr * AS_STRIDE + lkh) * 4;
#pragma unroll
                for (int q = 0; q < 4; q++) cpa16(dA + q * 16, hp + q * 4);
                const unsigned* wp = g_w1_t + (size_t)(kc * 32 + lbk) * HID + lbn;
                unsigned dB = sB + (lbk * BS_STRIDE + lbn) * 4;
#pragma unroll
                for (int q = 0; q < 4; q++) cpa16(dB + q * 16, wp + q * 4);
            } else {
                const unsigned* wp = g_w2_t + (size_t)((kc - 8) * 32 + lbk) * HID + lbn;
                unsigned dB = sB + (lbk * BS_STRIDE + lbn) * 4;
#pragma unroll
                for (int q = 0; q < 4; q++) cpa16(dB + q * 16, wp + q * 4);
            }
        }
        CP_COMMIT();
    };

    // prologue: chunks 0,1,2 in flight
    issue_chunk(0);
    issue_chunk(1);
    issue_chunk(2);

    float acc[4][4][4];
#pragma unroll
    for (int mt = 0; mt < 4; mt++)
#pragma unroll
        for (int nt = 0; nt < 4; nt++)
#pragma unroll
            for (int j = 0; j < 4; j++) acc[mt][nt][j] = 0.0f;

    // ================= GEMM1: 8 chunks =================
#pragma unroll 1
    for (int kc = 0; kc < 8; kc++) {
        CP_WAIT2();
        __syncthreads();
        issue_chunk(kc + 3);
        const float* stA = sm + (kc & 3) * STAGE_FLOATS;
        const float* stB = stA + STAGE_A_FLOATS;
#pragma unroll
        for (int ks = 0; ks < 4; ks++) {
            unsigned a[4][4], b[4][2];
            const float* arow = stA + (mg * 64 + g) * AS_STRIDE + ks * 8 + t;
#pragma unroll
            for (int mt = 0; mt < 4; mt++) {
                const float* ap = arow + mt * 16 * AS_STRIDE;
                a[mt][0] = __float_as_uint(ap[0]);
                a[mt][1] = __float_as_uint(ap[8 * AS_STRIDE]);
                a[mt][2] = __float_as_uint(ap[4]);
                a[mt][3] = __float_as_uint(ap[8 * AS_STRIDE + 4]);
            }
            const float* bp = stB + (ks * 8 + t) * BS_STRIDE + ng * 32 + g;
#pragma unroll
            for (int nt = 0; nt < 4; nt++) {
                b[nt][0] = __float_as_uint(bp[nt * 8]);
                b[nt][1] = __float_as_uint(bp[4 * BS_STRIDE + nt * 8]);
            }
#pragma unroll
            for (int mt = 0; mt < 4; mt++)
#pragma unroll
                for (int nt = 0; nt < 4; nt++)
                    mma8(acc[mt][nt], a[mt], b[nt]);
        }
    }

    // ===== epilogue1: bias + SiLU -> P chunks (tf32, fragment layout) =====
    {
        float* pc = sm + P_OFF + ng * PCH_FLOATS;
#pragma unroll
        for (int mt = 0; mt < 4; mt++) {
#pragma unroll
            for (int nt = 0; nt < 4; nt++) {
                int colb = ng * 32 + nt * 8 + 2 * t;
                float bz0 = __ldg(eb1 + colb), bz1 = __ldg(eb1 + colb + 1);
                int r0 = mg * 64 + mt * 16 + g;
                uint2 v0, v1;
                v0.x = tf32_of(silu_f(acc[mt][nt][0] + bz0));
                v0.y = tf32_of(silu_f(acc[mt][nt][1] + bz1));
                v1.x = tf32_of(silu_f(acc[mt][nt][2] + bz0));
                v1.y = tf32_of(silu_f(acc[mt][nt][3] + bz1));
                *(uint2*)(pc + r0 * AS_STRIDE + nt * 8 + 2 * t) = v0;
                *(uint2*)(pc + (r0 + 8) * AS_STRIDE + nt * 8 + 2 * t) = v1;
                acc[mt][nt][0] = 0.0f; acc[mt][nt][1] = 0.0f;
                acc[mt][nt][2] = 0.0f; acc[mt][nt][3] = 0.0f;
            }
        }
    }

    // ================= GEMM2: 4 chunks; A = P (SMEM), B from pipeline =================
#pragma unroll 1
    for (int c = 0; c < 4; c++) {
        CP_WAIT2();
        __syncthreads();          // also orders epilogue1 P writes before P reads (c==0)
        issue_chunk(11 + c);      // 11 real, 12..14 empty commits keep the count
        const float* pc  = sm + P_OFF + c * PCH_FLOATS;
        const float* stB = sm + ((8 + c) & 3) * STAGE_FLOATS + STAGE_A_FLOATS;
#pragma unroll
        for (int ks = 0; ks < 4; ks++) {
            unsigned a[4][4], b[4][2];
            const float* arow = pc + (mg * 64 + g) * AS_STRIDE + ks * 8 + t;
#pragma unroll
            for (int mt = 0; mt < 4; mt++) {
                const float* ap = arow + mt * 16 * AS_STRIDE;
                a[mt][0] = __float_as_uint(ap[0]);
                a[mt][1] = __float_as_uint(ap[8 * AS_STRIDE]);
                a[mt][2] = __float_as_uint(ap[4]);
                a[mt][3] = __float_as_uint(ap[8 * AS_STRIDE + 4]);
            }
            const float* bp = stB + (ks * 8 + t) * BS_STRIDE + ng * 32 + g;
#pragma unroll
            for (int nt = 0; nt < 4; nt++) {
                b[nt][0] = __float_as_uint(bp[nt * 8]);
                b[nt][1] = __float_as_uint(bp[4 * BS_STRIDE + nt * 8]);
            }
#pragma unroll
            for (int mt = 0; mt < 4; mt++)
#pragma unroll
                for (int nt = 0; nt < 4; nt++)
                    mma8(acc[mt][nt], a[mt], b[nt]);
        }
    }
    __syncthreads();

    // ===== epilogue2: bias + SiLU -> stage (fp32, P chunk c) -> coalesced mij + atomics =====
#pragma unroll 1
    for (int c = 0; c < 4; c++) {
        float* pc = sm + P_OFF + c * PCH_FLOATS;
        if (ng == c) {
#pragma unroll
            for (int mt = 0; mt < 4; mt++) {
#pragma unroll
                for (int nt = 0; nt < 4; nt++) {
                    int colb = ng * 32 + nt * 8 + 2 * t;
                    float bz0 = __ldg(eb2 + colb), bz1 = __ldg(eb2 + colb + 1);
                    int r0 = mg * 64 + mt * 16 + g;
                    float2 v0, v1;
                    v0.x = silu_f(acc[mt][nt][0] + bz0);
                    v0.y = silu_f(acc[mt][nt][1] + bz1);
                    v1.x = silu_f(acc[mt][nt][2] + bz0);
                    v1.y = silu_f(acc[mt][nt][3] + bz1);
                    *(float2*)(pc + r0 * AS_STRIDE + nt * 8 + 2 * t) = v0;
                    *(float2*)(pc + (r0 + 8) * AS_STRIDE + nt * 8 + 2 * t) = v1;
                }
            }
        }
        __syncthreads();
#pragma unroll 1
        for (int i = 0; i < 16; i++) {
            int r = wid * 16 + i;
            float v = pc[r * AS_STRIDE + lane];
            mij[(size_t)(e0 + r) * HID + c * 32 + lane] = v;
            atomicAdd(agg + (size_t)rs[r] * HID + c * 32 + lane, v);
        }
        __syncthreads();
    }
}

// Node MLP (fp32 FFMA, small)
#define TE 64
#define KT 16
__global__ __launch_bounds__(THREADS) void node_kernel(
    const float* __restrict__ h,
    const float* __restrict__ nw1, const float* __restrict__ nb1,
    const float* __restrict__ nw2, const float* __restrict__ nb2,
    float* __restrict__ out)
{
    __shared__ float as[TE][KT];
    __shared__ float bs[KT][HID];
    __shared__ float hs[TE][HID];

    const int tid = threadIdx.x;
    const int v0 = blockIdx.x * TE;
    const int tx = tid & 15;
    const int ty = tid >> 4;
    const int r0 = ty * 4;
    const int c0 = tx * 8;

    float b1r[8], b2r[8];
#pragma unroll
    for (int j = 0; j < 8; j++) { b1r[j] = nb1[c0 + j]; b2r[j] = nb2[c0 + j]; }

    float acc[4][8];
#pragma unroll
    for (int i = 0; i < 4; i++)
#pragma unroll
        for (int j = 0; j < 8; j++) acc[i][j] = 0.0f;

    for (int k0 = 0; k0 < NF + HID; k0 += KT) {
        __syncthreads();
        {
            int e = tid >> 2;
            int kq = (tid & 3) * 4;
            int node = v0 + e;
            if (node >= N_NODES) node = N_NODES - 1;
            float4 v;
            if (k0 < NF) {
                v = *(const float4*)(h + node * NF + k0 + kq);
            } else {
                v = *(const float4*)(out + (size_t)node * HID + (k0 - NF) + kq);
                v.x *= INV_NORM; v.y *= INV_NORM; v.z *= INV_NORM; v.w *= INV_NORM;
            }
            *(float4*)&as[e][kq] = v;
        }
#pragma unroll
        for (int j = 0; j < 2; j++) {
            int lin = tid + j * THREADS;
            int k = lin >> 5, c4 = (lin & 31) * 4;
            *(float4*)&bs[k][c4] = *(const float4*)(nw1 + (k0 + k) * HID + c4);
        }
        __syncthreads();
#pragma unroll
        for (int k = 0; k < KT; k++) {
            float a0 = as[r0 + 0][k], a1 = as[r0 + 1][k];
            float a2 = as[r0 + 2][k], a3 = as[r0 + 3][k];
            float4 b0 = *(float4*)&bs[k][c0];
            float4 b1 = *(float4*)&bs[k][c0 + 4];
            float bb[8] = {b0.x, b0.y, b0.z, b0.w, b1.x, b1.y, b1.z, b1.w};
#pragma unroll
            for (int j = 0; j < 8; j++) {
                acc[0][j] = fmaf(a0, bb[j], acc[0][j]);
                acc[1][j] = fmaf(a1, bb[j], acc[1][j]);
                acc[2][j] = fmaf(a2, bb[j], acc[2][j]);
                acc[3][j] = fmaf(a3, bb[j], acc[3][j]);
            }
        }
    }

#pragma unroll
    for (int i = 0; i < 4; i++)
#pragma unroll
        for (int j = 0; j < 8; j++) {
            hs[r0 + i][c0 + j] = silu_f(acc[i][j] + b1r[j]);
            acc[i][j] = 0.0f;
        }
    __syncthreads();

    for (int k0 = 0; k0 < HID; k0 += KT) {
        __syncthreads();
#pragma unroll
        for (int j = 0; j < 2; j++) {
            int lin = tid + j * THREADS;
            int k = lin >> 5, c4 = (lin & 31) * 4;
            *(float4*)&bs[k][c4] = *(const float4*)(nw2 + (k0 + k) * HID + c4);
        }
        __syncthreads();
#pragma unroll
        for (int k = 0; k < KT; k++) {
            float a0 = hs[r0 + 0][k0 + k], a1 = hs[r0 + 1][k0 + k];
            float a2 = hs[r0 + 2][k0 + k], a3 = hs[r0 + 3][k0 + k];
            float4 b0 = *(float4*)&bs[k][c0];
            float4 b1 = *(float4*)&bs[k][c0 + 4];
            float bb[8] = {b0.x, b0.y, b0.z, b0.w, b1.x, b1.y, b1.z, b1.w};
#pragma unroll
            for (int j = 0; j < 8; j++) {
                acc[0][j] = fmaf(a0, bb[j], acc[0][j]);
                acc[1][j] = fmaf(a1, bb[j], acc[1][j]);
                acc[2][j] = fmaf(a2, bb[j], acc[2][j]);
                acc[3][j] = fmaf(a3, bb[j], acc[3][j]);
            }
        }
    }

#pragma unroll
    for (int i = 0; i < 4; i++) {
        int node = v0 + r0 + i;
        if (node < N_NODES) {
#pragma unroll
            for (int jj = 0; jj < 8; jj += 4) {
                int c = c0 + jj;
                const float4 hv = *(const float4*)(h + node * NF + c);
                float4 v;
                v.x = hv.x + acc[i][jj + 0] + b2r[jj + 0];
                v.y = hv.y + acc[i][jj + 1] + b2r[jj + 1];
                v.z = hv.z + acc[i][jj + 2] + b2r[jj + 2];
                v.w = hv.w + acc[i][jj + 3] + b2r[jj + 3];
                *(float4*)(out + (size_t)node * NF + c) = v;
            }
        }
    }
}

extern "C" void kernel_launch(void* const* d_in, const int* in_sizes, int n_in,
                              void* d_out, int out_size) {
    const float* h   = (const float*)d_in[0];
    const int*   ei  = (const int*)d_in[1];     // int32 [2, N_EDGES]
    const float* ew1 = (const float*)d_in[2];
    const float* eb1 = (const float*)d_in[3];
    const float* ew2 = (const float*)d_in[4];
    const float* eb2 = (const float*)d_in[5];
    const float* nw1 = (const float*)d_in[6];
    const float* nb1 = (const float*)d_in[7];
    const float* nw2 = (const float*)d_in[8];
    const float* nb2 = (const float*)d_in[9];

    float* out = (float*)d_out;                  // [N_NODES, NF] (also agg scratch)
    float* mij = out + (size_t)N_NODES * NF;     // [N_EDGES, HID]

    cudaFuncSetAttribute(edge_kernel_mma, cudaFuncAttributeMaxDynamicSharedMemorySize,
                         SMEM_BYTES);

    prep_kernel<<<(N_NODES * NF + 255) / 256, 256>>>(h, ew1, ew2, out);
    edge_kernel_mma<<<N_EDGES / 128, THREADS, SMEM_BYTES>>>(ei, eb1, eb2, mij, out);
    node_kernel<<<(N_NODES + TE - 1) / TE, THREADS>>>(h, nw1, nb1, nw2, nb2, out);
}

// round 16
// speedup vs baseline: 2.2217x; 1.2911x over previous
#include <cuda_runtime.h>

#define NF 128
#define HID 128
#define N_NODES 10000
#define N_EDGES 640000
#define THREADS 256
#define TE_E 64
#define INV_NORM 0.01f

// ---- SMEM layout (float offsets), M=64 tiles ----
#define AS_STRIDE 36                      // 32 k + 4 pad; %32==4 -> conflict-free A frags
#define BS_STRIDE 136                     // 128 n + 8 pad; %32==8 -> conflict-free B frags
#define A_ST_FLOATS (TE_E * AS_STRIDE)    // 2304
#define B_ST_FLOATS (32 * BS_STRIDE)      // 4352
#define A_OFF 0                           // 2 stages: 0, 2304
#define B_OFF (2 * A_ST_FLOATS)           // 4608; stages at +0, +4352
#define P_OFF (B_OFF + 2 * B_ST_FLOATS)   // 13312; 4 chunks x 2304
#define RS_OFF (P_OFF + 4 * A_ST_FLOATS)  // 22528
#define CS_OFF (RS_OFF + TE_E)
#define SMEM_FLOATS (CS_OFF + TE_E)       // 22656
#define SMEM_BYTES (SMEM_FLOATS * 4)      // 90624 B -> 2 CTAs/SM

// tf32 scratch (pre-converted once per launch)
__device__ unsigned g_h_t[N_NODES * NF];
__device__ unsigned g_w1_t[2 * NF * HID];
__device__ unsigned g_w2_t[HID * HID];

__device__ __forceinline__ float silu_f(float x) { return x / (1.0f + __expf(-x)); }

__device__ __forceinline__ unsigned tf32_of(float f) {
    unsigned r;
    asm("cvt.rna.tf32.f32 %0, %1;" : "=r"(r) : "f"(f));
    return r;
}

__device__ __forceinline__ unsigned smem_u32(const void* p) {
    unsigned a;
    asm("{ .reg .u64 t; cvta.to.shared.u64 t, %1; cvt.u32.u64 %0, t; }" : "=r"(a) : "l"(p));
    return a;
}

__device__ __forceinline__ void cpa16(unsigned dst, const void* src) {
    asm volatile("cp.async.ca.shared.global [%0], [%1], 16;" :: "r"(dst), "l"(src));
}
#define CP_COMMIT() asm volatile("cp.async.commit_group;" ::: "memory")
#define CP_WAIT1()  asm volatile("cp.async.wait_group 1;" ::: "memory")

__device__ __forceinline__ void mma8(float* c, const unsigned* a, const unsigned* b) {
    asm volatile(
        "mma.sync.aligned.m16n8k8.row.col.f32.tf32.tf32.f32 "
        "{%0,%1,%2,%3}, {%4,%5,%6,%7}, {%8,%9}, {%0,%1,%2,%3};"
        : "+f"(c[0]), "+f"(c[1]), "+f"(c[2]), "+f"(c[3])
        : "r"(a[0]), "r"(a[1]), "r"(a[2]), "r"(a[3]), "r"(b[0]), "r"(b[1]));
}

// Fused prep: convert h/ew1/ew2 to tf32 scratch + zero agg (= out region).
__global__ void prep_kernel(const float* __restrict__ h,
                            const float* __restrict__ ew1,
                            const float* __restrict__ ew2,
                            float* __restrict__ out) {
    int i = blockIdx.x * blockDim.x + threadIdx.x;
    if (i < N_NODES * NF) {
        g_h_t[i] = tf32_of(h[i]);
        out[i] = 0.0f;
    }
    if (i < 2 * NF * HID) g_w1_t[i] = tf32_of(ew1[i]);
    if (i < HID * HID)    g_w2_t[i] = tf32_of(ew2[i]);
}

// no-op pad launch: makes launches/call = 4 so ncu (-s 5 -c 1) lands on edge_kernel
__global__ void profile_pad_kernel() {}

// Edge MLP via mma.sync tf32, 64 edges/CTA, occupancy 2.
// 8 warps = 2(m: 32 rows) x 4(n: 32 cols); acc[2][4][4].
__global__ __launch_bounds__(THREADS, 2) void edge_kernel_mma(
    const int* __restrict__ ei,
    const float* __restrict__ eb1, const float* __restrict__ eb2,
    float* __restrict__ mij, float* __restrict__ agg)
{
    extern __shared__ float sm[];
    int* rs = (int*)(sm + RS_OFF);
    int* cs = (int*)(sm + CS_OFF);
    const unsigned sbase = smem_u32(sm);

    const int tid = threadIdx.x;
    const int wid = tid >> 5, lane = tid & 31;
    const int g = lane >> 2, t = lane & 3;
    const int mg = wid & 1, ng = wid >> 1;
    const int e0 = blockIdx.x * TE_E;

    if (tid < TE_E) {
        rs[tid] = ei[e0 + tid];
        cs[tid] = ei[N_EDGES + e0 + tid];
    }
    __syncthreads();

    // loader mappings
    const int lr = tid >> 2, lq = (tid & 3) * 8;     // A: row 0..63, 8-float quarter
    const int lbk = tid >> 3, lbn = (tid & 7) * 16;  // B: k row 0..31, n base

    // chunk kc: 0..7 GEMM1 (A+B), 8..11 GEMM2 (B only), >=12 empty commit
    auto issue_chunk = [&](int kc) {
        if (kc < 12) {
            unsigned dB = sbase + (B_OFF + (kc & 1) * B_ST_FLOATS + lbk * BS_STRIDE + lbn) * 4;
            if (kc < 8) {
                int node = (kc < 4) ? rs[lr] : cs[lr];
                const unsigned* hp = g_h_t + (size_t)node * NF + (kc & 3) * 32 + lq;
                unsigned dA = sbase + ((kc & 1) * A_ST_FLOATS + lr * AS_STRIDE + lq) * 4;
                cpa16(dA, hp);
                cpa16(dA + 16, hp + 4);
                const unsigned* wp = g_w1_t + (size_t)(kc * 32 + lbk) * HID + lbn;
#pragma unroll
                for (int q = 0; q < 4; q++) cpa16(dB + q * 16, wp + q * 4);
            } else {
                const unsigned* wp = g_w2_t + (size_t)((kc - 8) * 32 + lbk) * HID + lbn;
#pragma unroll
                for (int q = 0; q < 4; q++) cpa16(dB + q * 16, wp + q * 4);
            }
        }
        CP_COMMIT();
    };

    float acc[2][4][4];
#pragma unroll
    for (int mt = 0; mt < 2; mt++)
#pragma unroll
        for (int nt = 0; nt < 4; nt++)
#pragma unroll
            for (int j = 0; j < 4; j++) acc[mt][nt][j] = 0.0f;

    auto mma_phase = [&](const float* stA, const float* stB) {
#pragma unroll
        for (int ks = 0; ks < 4; ks++) {
            unsigned a[2][4], b[4][2];
            const float* arow = stA + (mg * 32 + g) * AS_STRIDE + ks * 8 + t;
#pragma unroll
            for (int mt = 0; mt < 2; mt++) {
                const float* ap = arow + mt * 16 * AS_STRIDE;
                a[mt][0] = __float_as_uint(ap[0]);
                a[mt][1] = __float_as_uint(ap[8 * AS_STRIDE]);
                a[mt][2] = __float_as_uint(ap[4]);
                a[mt][3] = __float_as_uint(ap[8 * AS_STRIDE + 4]);
            }
            const float* bp = stB + (ks * 8 + t) * BS_STRIDE + ng * 32 + g;
#pragma unroll
            for (int nt = 0; nt < 4; nt++) {
                b[nt][0] = __float_as_uint(bp[nt * 8]);
                b[nt][1] = __float_as_uint(bp[4 * BS_STRIDE + nt * 8]);
            }
#pragma unroll
            for (int mt = 0; mt < 2; mt++)
#pragma unroll
                for (int nt = 0; nt < 4; nt++)
                    mma8(acc[mt][nt], a[mt], b[nt]);
        }
    };

    // prologue: chunks 0,1 in flight
    issue_chunk(0);
    issue_chunk(1);

    // ================= GEMM1: 8 chunks, 2-stage ring =================
#pragma unroll 1
    for (int kc = 0; kc < 8; kc++) {
        CP_WAIT1();          // chunk kc complete (only kc+1 outstanding)
        __syncthreads();
        mma_phase(sm + (kc & 1) * A_ST_FLOATS,
                  sm + B_OFF + (kc & 1) * B_ST_FLOATS);
        __syncthreads();     // all warps done with stage kc&1
        issue_chunk(kc + 2); // overwrite freed stage; overlaps compute of kc+1
    }

    // ===== epilogue1: bias + SiLU -> P chunk ng (tf32, fragment layout) =====
    {
        float* pc = sm + P_OFF + ng * A_ST_FLOATS;
#pragma unroll
        for (int mt = 0; mt < 2; mt++) {
#pragma unroll
            for (int nt = 0; nt < 4; nt++) {
                int colb = ng * 32 + nt * 8 + 2 * t;
                float bz0 = __ldg(eb1 + colb), bz1 = __ldg(eb1 + colb + 1);
                int r0 = mg * 32 + mt * 16 + g;
                uint2 v0, v1;
                v0.x = tf32_of(silu_f(acc[mt][nt][0] + bz0));
                v0.y = tf32_of(silu_f(acc[mt][nt][1] + bz1));
                v1.x = tf32_of(silu_f(acc[mt][nt][2] + bz0));
                v1.y = tf32_of(silu_f(acc[mt][nt][3] + bz1));
                *(uint2*)(pc + r0 * AS_STRIDE + nt * 8 + 2 * t) = v0;
                *(uint2*)(pc + (r0 + 8) * AS_STRIDE + nt * 8 + 2 * t) = v1;
                acc[mt][nt][0] = 0.0f; acc[mt][nt][1] = 0.0f;
                acc[mt][nt][2] = 0.0f; acc[mt][nt][3] = 0.0f;
            }
        }
    }

    // ================= GEMM2: 4 chunks; A = P chunk c, B from ring =================
#pragma unroll 1
    for (int c = 0; c < 4; c++) {
        int kc = 8 + c;
        CP_WAIT1();
        __syncthreads();     // also orders epilogue1 P writes before P reads
        mma_phase(sm + P_OFF + c * A_ST_FLOATS,
                  sm + B_OFF + (kc & 1) * B_ST_FLOATS);
        __syncthreads();
        issue_chunk(kc + 2); // 10,11 real; 12,13 empty commits
    }

    // ===== epilogue2: bias + SiLU -> stage (fp32, P chunk c) -> coalesced mij + atomics =====
#pragma unroll 1
    for (int c = 0; c < 4; c++) {
        float* pc = sm + P_OFF + c * A_ST_FLOATS;
        if (ng == c) {
#pragma unroll
            for (int mt = 0; mt < 2; mt++) {
#pragma unroll
                for (int nt = 0; nt < 4; nt++) {
                    int colb = ng * 32 + nt * 8 + 2 * t;
                    float bz0 = __ldg(eb2 + colb), bz1 = __ldg(eb2 + colb + 1);
                    int r0 = mg * 32 + mt * 16 + g;
                    float2 v0, v1;
                    v0.x = silu_f(acc[mt][nt][0] + bz0);
                    v0.y = silu_f(acc[mt][nt][1] + bz1);
                    v1.x = silu_f(acc[mt][nt][2] + bz0);
                    v1.y = silu_f(acc[mt][nt][3] + bz1);
                    *(float2*)(pc + r0 * AS_STRIDE + nt * 8 + 2 * t) = v0;
                    *(float2*)(pc + (r0 + 8) * AS_STRIDE + nt * 8 + 2 * t) = v1;
                }
            }
        }
        __syncthreads();
        // cooperative: warp w handles rows w*8..w*8+7; lane = column within 32-chunk
#pragma unroll 1
        for (int i = 0; i < 8; i++) {
            int r = wid * 8 + i;
            float v = pc[r * AS_STRIDE + lane];
            mij[(size_t)(e0 + r) * HID + c * 32 + lane] = v;
            atomicAdd(agg + (size_t)rs[r] * HID + c * 32 + lane, v);
        }
        __syncthreads();
    }
}

// Node MLP (fp32 FFMA, small)
#define TE 64
#define KT 16
__global__ __launch_bounds__(THREADS) void node_kernel(
    const float* __restrict__ h,
    const float* __restrict__ nw1, const float* __restrict__ nb1,
    const float* __restrict__ nw2, const float* __restrict__ nb2,
    float* __restrict__ out)
{
    __shared__ float as[TE][KT];
    __shared__ float bs[KT][HID];
    __shared__ float hs[TE][HID];

    const int tid = threadIdx.x;
    const int v0 = blockIdx.x * TE;
    const int tx = tid & 15;
    const int ty = tid >> 4;
    const int r0 = ty * 4;
    const int c0 = tx * 8;

    float b1r[8], b2r[8];
#pragma unroll
    for (int j = 0; j < 8; j++) { b1r[j] = nb1[c0 + j]; b2r[j] = nb2[c0 + j]; }

    float acc[4][8];
#pragma unroll
    for (int i = 0; i < 4; i++)
#pragma unroll
        for (int j = 0; j < 8; j++) acc[i][j] = 0.0f;

    for (int k0 = 0; k0 < NF + HID; k0 += KT) {
        __syncthreads();
        {
            int e = tid >> 2;
            int kq = (tid & 3) * 4;
            int node = v0 + e;
            if (node >= N_NODES) node = N_NODES - 1;
            float4 v;
            if (k0 < NF) {
                v = *(const float4*)(h + node * NF + k0 + kq);
            } else {
                v = *(const float4*)(out + (size_t)node * HID + (k0 - NF) + kq);
                v.x *= INV_NORM; v.y *= INV_NORM; v.z *= INV_NORM; v.w *= INV_NORM;
            }
            *(float4*)&as[e][kq] = v;
        }
#pragma unroll
        for (int j = 0; j < 2; j++) {
            int lin = tid + j * THREADS;
            int k = lin >> 5, c4 = (lin & 31) * 4;
            *(float4*)&bs[k][c4] = *(const float4*)(nw1 + (k0 + k) * HID + c4);
        }
        __syncthreads();
#pragma unroll
        for (int k = 0; k < KT; k++) {
            float a0 = as[r0 + 0][k], a1 = as[r0 + 1][k];
            float a2 = as[r0 + 2][k], a3 = as[r0 + 3][k];
            float4 b0 = *(float4*)&bs[k][c0];
            float4 b1 = *(float4*)&bs[k][c0 + 4];
            float bb[8] = {b0.x, b0.y, b0.z, b0.w, b1.x, b1.y, b1.z, b1.w};
#pragma unroll
            for (int j = 0; j < 8; j++) {
                acc[0][j] = fmaf(a0, bb[j], acc[0][j]);
                acc[1][j] = fmaf(a1, bb[j], acc[1][j]);
                acc[2][j] = fmaf(a2, bb[j], acc[2][j]);
                acc[3][j] = fmaf(a3, bb[j], acc[3][j]);
            }
        }
    }

#pragma unroll
    for (int i = 0; i < 4; i++)
#pragma unroll
        for (int j = 0; j < 8; j++) {
            hs[r0 + i][c0 + j] = silu_f(acc[i][j] + b1r[j]);
            acc[i][j] = 0.0f;
        }
    __syncthreads();

    for (int k0 = 0; k0 < HID; k0 += KT) {
        __syncthreads();
#pragma unroll
        for (int j = 0; j < 2; j++) {
            int lin = tid + j * THREADS;
            int k = lin >> 5, c4 = (lin & 31) * 4;
            *(float4*)&bs[k][c4] = *(const float4*)(nw2 + (k0 + k) * HID + c4);
        }
        __syncthreads();
#pragma unroll
        for (int k = 0; k < KT; k++) {
            float a0 = hs[r0 + 0][k0 + k], a1 = hs[r0 + 1][k0 + k];
            float a2 = hs[r0 + 2][k0 + k], a3 = hs[r0 + 3][k0 + k];
            float4 b0 = *(float4*)&bs[k][c0];
            float4 b1 = *(float4*)&bs[k][c0 + 4];
            float bb[8] = {b0.x, b0.y, b0.z, b0.w, b1.x, b1.y, b1.z, b1.w};
#pragma unroll
            for (int j = 0; j < 8; j++) {
                acc[0][j] = fmaf(a0, bb[j], acc[0][j]);
                acc[1][j] = fmaf(a1, bb[j], acc[1][j]);
                acc[2][j] = fmaf(a2, bb[j], acc[2][j]);
                acc[3][j] = fmaf(a3, bb[j], acc[3][j]);
            }
        }
    }

#pragma unroll
    for (int i = 0; i < 4; i++) {
        int node = v0 + r0 + i;
        if (node < N_NODES) {
#pragma unroll
            for (int jj = 0; jj < 8; jj += 4) {
                int c = c0 + jj;
                const float4 hv = *(const float4*)(h + node * NF + c);
                float4 v;
                v.x = hv.x + acc[i][jj + 0] + b2r[jj + 0];
                v.y = hv.y + acc[i][jj + 1] + b2r[jj + 1];
                v.z = hv.z + acc[i][jj + 2] + b2r[jj + 2];
                v.w = hv.w + acc[i][jj + 3] + b2r[jj + 3];
                *(float4*)(out + (size_t)node * NF + c) = v;
            }
        }
    }
}

extern "C" void kernel_launch(void* const* d_in, const int* in_sizes, int n_in,
                              void* d_out, int out_size) {
    const float* h   = (const float*)d_in[0];
    const int*   ei  = (const int*)d_in[1];     // int32 [2, N_EDGES]
    const float* ew1 = (const float*)d_in[2];
    const float* eb1 = (const float*)d_in[3];
    const float* ew2 = (const float*)d_in[4];
    const float* eb2 = (const float*)d_in[5];
    const float* nw1 = (const float*)d_in[6];
    const float* nb1 = (const float*)d_in[7];
    const float* nw2 = (const float*)d_in[8];
    const float* nb2 = (const float*)d_in[9];

    float* out = (float*)d_out;                  // [N_NODES, NF] (also agg scratch)
    float* mij = out + (size_t)N_NODES * NF;     // [N_EDGES, HID]

    cudaFuncSetAttribute(edge_kernel_mma, cudaFuncAttributeMaxDynamicSharedMemorySize,
                         SMEM_BYTES);

    prep_kernel<<<(N_NODES * NF + 255) / 256, 256>>>(h, ew1, ew2, out);
    edge_kernel_mma<<<N_EDGES / TE_E, THREADS, SMEM_BYTES>>>(ei, eb1, eb2, mij, out);
    node_kernel<<<(N_NODES + TE - 1) / TE, THREADS>>>(h, nw1, nb1, nw2, nb2, out);
    profile_pad_kernel<<<1, 1>>>();   // aligns ncu -s 5 -c 1 onto edge_kernel_mma
}